// round 4
// baseline (speedup 1.0000x reference)
#include <cuda_runtime.h>
#include <cuda_bf16.h>
#include <math.h>

// ---------------------------------------------------------------------------
// WITRAN 2D-PSGMU encoder.
//   input (32,48,24,32), W (1536,544), Bp (1536)
//   B=32, R=24 (cols), Lorig=48 (rows), L=71, H=256, C=32, K=2H+C=544
//   M = R*B = 768 sequences, per step: gate = [h_row,h_col,x] @ W^T (+ mask*Bp)
// Outputs (assumed concatenated flat fp32):
//   output_all  (768,71,512)       27,918,336
//   hidden_col  (32,1,48,256)         393,216   (copies from output_all)
//   hidden_row  (32,1,24,256)         196,608   (copies from output_all)
// ---------------------------------------------------------------------------

#define NB     32
#define RR_    24
#define LORIG  48
#define LL     71
#define HH     256
#define CC     32
#define KK_TOT 544
#define MM     768
#define NW     384            // 6 gates * 64 cols per CTA
#define OFF1   27918336
#define OFF2   28311552

// carry buffers (double-buffered over step parity) + transposed weights
__device__ float g_h_row[2][MM * HH];
__device__ float g_h_col[2][MM * HH];
__device__ float g_Wt[KK_TOT * 1536];     // Wt[k][j] = W[j][k]

// smem: As[544][36] floats + Bs[2][32][384] floats
#define AS_STRIDE 36
#define AS_FLOATS (KK_TOT * AS_STRIDE)      // 19584
#define BS_FLOATS (2 * 32 * NW)             // 24576
#define SMEM_BYTES ((AS_FLOATS + BS_FLOATS) * 4)

__device__ __forceinline__ float sigf(float x) { return 1.0f / (1.0f + expf(-x)); }

#define FMA2(acc, a, b) asm("fma.rn.f32x2 %0, %1, %2, %0;" : "+l"(acc) : "l"(a), "l"(b))

// ---------------------------------------------------------------------------
__global__ void witran_init_kernel(const float* __restrict__ W) {
    int idx = blockIdx.x * blockDim.x + threadIdx.x;
    int stride = gridDim.x * blockDim.x;
    for (int i = idx; i < MM * HH; i += stride) {
        g_h_row[0][i] = 0.0f;
        g_h_col[0][i] = 0.0f;
    }
    for (int i = idx; i < KK_TOT * 1536; i += stride) {
        int j = i % 1536;
        int k = i / 1536;
        g_Wt[i] = W[j * KK_TOT + k];
    }
}

// ---------------------------------------------------------------------------
// One recurrence step. grid (4,24): blockIdx.x = 64-col hidden tile,
// blockIdx.y = r (32 consecutive n-rows share one r). 256 threads.
__global__ void __launch_bounds__(256, 1)
witran_step_kernel(int s, const float* __restrict__ input,
                   const float* __restrict__ Bp, float* __restrict__ out) {
    extern __shared__ float sm[];
    float* As = sm;                    // [544][36], k-major
    float* Bs = sm + AS_FLOATS;        // [2][32][384]

    const int tid = threadIdx.x;
    const int k0  = blockIdx.x << 6;   // hidden col tile base (0,64,128,192)
    const int rr  = blockIdx.y;        // r for all rows of this CTA
    const int m0  = rr << 5;           // n base
    const int cur = s & 1, nxt = cur ^ 1;
    const int l   = s - rr;            // x time index for this r

    // ---- load A tile: A[n][k] with k = [h_row(256) | h_col(256) | x(32)]
    for (int i = tid; i < 32 * KK_TOT; i += 256) {
        int nl = i / KK_TOT;
        int k  = i - nl * KK_TOT;
        int n  = m0 + nl;
        float v;
        if (k < 256)       v = g_h_row[cur][n * HH + k];
        else if (k < 512)  v = g_h_col[cur][n * HH + (k - 256)];
        else {
            int c = k - 512;           // b == nl since n = rr*32 + nl
            v = (l >= 0 && l < LORIG)
                ? input[((nl * LORIG + l) * RR_ + rr) * CC + c] : 0.0f;
        }
        As[k * AS_STRIDE + nl] = v;
    }

    // ---- cp.async prefetch of one 32-deep K chunk of W^T (384 cols)
    auto prefetch = [&](int t) {
        int kbase = t * 32;
        float* dstb = Bs + (t & 1) * (32 * NW);
#pragma unroll
        for (int i = 0; i < 12; ++i) {
            int idx4 = tid + (i << 8);
            int kk = idx4 / 96;
            int c6 = (idx4 - kk * 96) << 2;      // 0..380 step 4
            int g = c6 >> 6, c = c6 & 63;
            const float* src = g_Wt + (kbase + kk) * 1536 + g * 256 + k0 + c;
            unsigned dst = (unsigned)__cvta_generic_to_shared(dstb + kk * NW + c6);
            asm volatile("cp.async.cg.shared.global [%0], [%1], 16;" :: "r"(dst), "l"(src));
        }
    };

    prefetch(0);
    asm volatile("cp.async.commit_group;");

    unsigned long long acc[24];
#pragma unroll
    for (int q = 0; q < 24; ++q) acc[q] = 0ull;

    const int ty = tid >> 5;           // 0..7 -> 4 rows each
    const int tk = tid & 31;           // col pair (2*tk, 2*tk+1) per gate

    for (int t = 0; t < 17; ++t) {
        if (t < 16) {
            prefetch(t + 1);
            asm volatile("cp.async.commit_group;");
            asm volatile("cp.async.wait_group 1;");
        } else {
            asm volatile("cp.async.wait_group 0;");
        }
        __syncthreads();
        const float* Bsb = Bs + (t & 1) * (32 * NW);
        const int kb = t * 32;
#pragma unroll 4
        for (int kk = 0; kk < 32; ++kk) {
            const float4 av = *(const float4*)(As + (kb + kk) * AS_STRIDE + (ty << 2));
            unsigned long long a0, a1, a2, a3;
            asm("mov.b64 %0,{%1,%1};" : "=l"(a0) : "r"(__float_as_uint(av.x)));
            asm("mov.b64 %0,{%1,%1};" : "=l"(a1) : "r"(__float_as_uint(av.y)));
            asm("mov.b64 %0,{%1,%1};" : "=l"(a2) : "r"(__float_as_uint(av.z)));
            asm("mov.b64 %0,{%1,%1};" : "=l"(a3) : "r"(__float_as_uint(av.w)));
            const unsigned long long* br =
                (const unsigned long long*)(Bsb + kk * NW) + tk;
#pragma unroll
            for (int g = 0; g < 6; ++g) {
                unsigned long long b2 = br[g * 32];
                FMA2(acc[g * 4 + 0], a0, b2);
                FMA2(acc[g * 4 + 1], a1, b2);
                FMA2(acc[g * 4 + 2], a2, b2);
                FMA2(acc[g * 4 + 3], a3, b2);
            }
        }
        __syncthreads();
    }

    // ---- epilogue: bias, activations, recurrence, stores
    const int kcol = k0 + (tk << 1);
    const bool bOn = (rr <= s) && (s < RR_);
    float bias[12];
#pragma unroll
    for (int g = 0; g < 6; ++g) {
        bias[2 * g]     = bOn ? Bp[g * 256 + kcol]     : 0.0f;
        bias[2 * g + 1] = bOn ? Bp[g * 256 + kcol + 1] : 0.0f;
    }

#pragma unroll
    for (int i = 0; i < 4; ++i) {
        int nl = (ty << 2) + i;
        int n  = m0 + nl;
        float gv[12];
#pragma unroll
        for (int g = 0; g < 6; ++g) {
            unsigned lo_u, hi_u;
            asm("mov.b64 {%0,%1}, %2;" : "=r"(lo_u), "=r"(hi_u) : "l"(acc[g * 4 + i]));
            gv[2 * g]     = __uint_as_float(lo_u) + bias[2 * g];
            gv[2 * g + 1] = __uint_as_float(hi_u) + bias[2 * g + 1];
        }
        float hr[2], hc[2];
#pragma unroll
        for (int c2 = 0; c2 < 2; ++c2) {
            float u_row = sigf(gv[0 + c2]);
            float o_row = sigf(gv[2 + c2]);
            float u_col = sigf(gv[4 + c2]);
            float o_col = sigf(gv[6 + c2]);
            float i_row = tanhf(gv[8 + c2]);
            float i_col = tanhf(gv[10 + c2]);
            float hro = As[(kcol + c2) * AS_STRIDE + nl];
            float hco = As[(256 + kcol + c2) * AS_STRIDE + nl];
            hr[c2] = tanhf((1.0f - u_row) * hro + u_row * i_row) * o_row;
            hc[c2] = tanhf((1.0f - u_col) * hco + u_col * i_col) * o_col;
        }
        size_t obase = ((size_t)n * LL + s) * 512 + kcol;
        *(float2*)(out + obase)       = make_float2(hr[0], hr[1]);
        *(float2*)(out + obase + 256) = make_float2(hc[0], hc[1]);
        *(float2*)(g_h_row[nxt] + n * HH + kcol) = make_float2(hr[0], hr[1]);
        int n2 = n + NB; if (n2 >= MM) n2 -= MM;          // roll(h_col, +B)
        *(float2*)(g_h_col[nxt] + n2 * HH + kcol) = make_float2(hc[0], hc[1]);
    }
}

// ---------------------------------------------------------------------------
__global__ void witran_gather_kernel(float* __restrict__ out) {
    int idx = blockIdx.x * blockDim.x + threadIdx.x;
    if (idx < 393216) {
        // hidden_col_all[b,0,t,k] = h_col_new(step 23+t, n=736+b)[k]
        int k = idx & 255;
        int t = (idx >> 8) % LORIG;
        int b = idx / (LORIG * 256);
        out[OFF1 + idx] = out[((size_t)(736 + b) * LL + 23 + t) * 512 + 256 + k];
    } else if (idx < 589824) {
        // hidden_row_all[b,0,i,k] = h_row(step 47+i, n=i*32+b)[k]
        int j = idx - 393216;
        int k = j & 255;
        int i = (j >> 8) % RR_;
        int b = j / (RR_ * 256);
        out[OFF2 + j] = out[((size_t)(i * NB + b) * LL + 47 + i) * 512 + k];
    }
}

// ---------------------------------------------------------------------------
extern "C" void kernel_launch(void* const* d_in, const int* in_sizes, int n_in,
                              void* d_out, int out_size) {
    const float* input = (const float*)d_in[0];
    const float* W     = (const float*)d_in[1];
    const float* Bp    = (const float*)d_in[2];
    float* out = (float*)d_out;

    cudaFuncSetAttribute(witran_step_kernel,
                         cudaFuncAttributeMaxDynamicSharedMemorySize, SMEM_BYTES);

    witran_init_kernel<<<1024, 256>>>(W);
    for (int s = 0; s < LL; ++s) {
        witran_step_kernel<<<dim3(4, 24), 256, SMEM_BYTES>>>(s, input, Bp, out);
    }
    witran_gather_kernel<<<2304, 256>>>(out);
}

// round 6
// speedup vs baseline: 2.9694x; 2.9694x over previous
#include <cuda_runtime.h>
#include <cuda_bf16.h>
#include <math.h>

// ---------------------------------------------------------------------------
// WITRAN 2D-PSGMU encoder — mma.sync tf32 version (compute_103-safe).
//   input (32,48,24,32) fp32, W (1536,544) fp32, Bp (1536) fp32
//   B=32, R=24, Lorig=48, L=71, H=256, C=32, K=544, M=R*B=768
// Per step: gate[768,1536] = [h_row|h_col|x] @ W^T (+mask*Bp), gated tanh
// recurrence fused in the same kernel (CTA owns all 6 gates for its units).
// ---------------------------------------------------------------------------

#define NB     32
#define RR_    24
#define LORIG  48
#define LL     71
#define HH     256
#define MM     768
#define OFF1   27918336
#define OFF2   28311552

__device__ __align__(1024) float g_h_row[2][MM * HH];
__device__ __align__(1024) float g_h_col[2][MM * HH];

// ---- smem (float offsets). A tiles 64x32 @ stride 36, B tiles 192x32 @ 36.
#define AS_ST   36
#define OFF_A0  0
#define OFF_A1  2304
#define OFF_B0  4608
#define OFF_B1  11520
#define SMEM_FLOATS 18432
#define SMEM_BYTES  (SMEM_FLOATS * 4)
#define CS_ST   200              // epilogue stage stride (reuses offset 0)

__device__ __forceinline__ float sigf(float x) {
    return __fdividef(1.0f, 1.0f + __expf(-x));
}
__device__ __forceinline__ float tanhf_(float x) {
    return 1.0f - __fdividef(2.0f, __expf(2.0f * x) + 1.0f);
}
__device__ __forceinline__ unsigned tf32c(float v) {
    unsigned r;
    asm("cvt.rna.tf32.f32 %0, %1;" : "=r"(r) : "f"(v));
    return r;
}

#define MMA_TF32(c, a, b0, b1) \
    asm volatile("mma.sync.aligned.m16n8k8.row.col.f32.tf32.tf32.f32 " \
        "{%0,%1,%2,%3},{%4,%5,%6,%7},{%8,%9},{%0,%1,%2,%3};" \
        : "+f"((c)[0]), "+f"((c)[1]), "+f"((c)[2]), "+f"((c)[3]) \
        : "r"((a)[0]), "r"((a)[1]), "r"((a)[2]), "r"((a)[3]), \
          "r"(b0), "r"(b1))

// ---------------------------------------------------------------------------
__global__ void witran_init_kernel() {
    int idx = blockIdx.x * blockDim.x + threadIdx.x;
    int stride = gridDim.x * blockDim.x;
    for (int i = idx; i < MM * HH; i += stride) {
        g_h_row[0][i] = 0.0f;
        g_h_col[0][i] = 0.0f;
    }
}

// ---------------------------------------------------------------------------
// grid (8, 12): blockIdx.x = 32-unit tile (u0), blockIdx.y = 64-row M tile.
// 256 threads = 8 warps, warp grid 2(M) x 4(N), warp tile 32 x 48.
__global__ void __launch_bounds__(256, 1)
witran_step_mma(int s, const float* __restrict__ input, const float* __restrict__ W,
                const float* __restrict__ Bp, float* __restrict__ out) {
    extern __shared__ float sm[];
    const unsigned sbase = (unsigned)__cvta_generic_to_shared(sm);

    const int tid  = threadIdx.x;
    const int wid  = tid >> 5, lane = tid & 31;
    const int g8   = lane >> 2, tg = lane & 3;      // mma fragment coords
    const int wm   = wid & 1,  wn = wid >> 1;       // warp tile coords
    const int u0   = blockIdx.x << 5;
    const int n0   = blockIdx.y << 6;
    const int cur  = s & 1, nxt = cur ^ 1;

    // ---- cp.async one 32-deep K chunk: A (64x32) + B (192x32) ------------
    auto prefetch = [&](int c) {
        const int buf = c & 1;
        const unsigned adst0 = sbase + (buf ? OFF_A1 : OFF_A0) * 4;
        const unsigned bdst0 = sbase + (buf ? OFF_B1 : OFF_B0) * 4;
#pragma unroll
        for (int i = 0; i < 8; ++i) {
            int idx = tid + (i << 8);
            if (idx < 512) {                         // A: row = idx>>3, 16B part
                int row = idx >> 3, part = idx & 7;
                const float* src; unsigned sz = 16;
                if (c < 8)
                    src = g_h_row[cur] + ((n0 + row) << 8) + (c << 5) + (part << 2);
                else if (c < 16)
                    src = g_h_col[cur] + ((n0 + row) << 8) + ((c - 8) << 5) + (part << 2);
                else {
                    int r = (n0 + row) >> 5, b = row & 31, l = s - r;
                    if (l >= 0 && l < LORIG)
                        src = input + (((b * LORIG + l) * RR_ + r) << 5) + (part << 2);
                    else { src = input; sz = 0; }    // zero-fill
                }
                unsigned dst = adst0 + (row * AS_ST + (part << 2)) * 4;
                asm volatile("cp.async.cg.shared.global [%0], [%1], 16, %2;"
                             :: "r"(dst), "l"(src), "r"(sz));
            } else {                                 // B: nloc = g*32+v <-> W row g*256+u0+v
                int k2 = idx - 512;
                int row = k2 >> 3, part = k2 & 7;
                int j = ((row >> 5) << 8) + u0 + (row & 31);
                const float* src = W + j * 544 + (c << 5) + (part << 2);
                unsigned dst = bdst0 + (row * AS_ST + (part << 2)) * 4;
                asm volatile("cp.async.cg.shared.global [%0], [%1], 16;"
                             :: "r"(dst), "l"(src));
            }
        }
        asm volatile("cp.async.commit_group;");
    };

    float c[2][6][4];
#pragma unroll
    for (int i = 0; i < 2; ++i)
#pragma unroll
        for (int j = 0; j < 6; ++j)
#pragma unroll
            for (int q = 0; q < 4; ++q) c[i][j][q] = 0.0f;

    prefetch(0);
    for (int t = 0; t < 17; ++t) {
        if (t < 16) { prefetch(t + 1); asm volatile("cp.async.wait_group 1;"); }
        else        { asm volatile("cp.async.wait_group 0;"); }
        __syncthreads();
        const float* Ab = sm + ((t & 1) ? OFF_A1 : OFF_A0);
        const float* Bb = sm + ((t & 1) ? OFF_B1 : OFF_B0);
#pragma unroll
        for (int q = 0; q < 4; ++q) {
            const int k0 = (q << 3) + tg;
            unsigned a[2][4];
#pragma unroll
            for (int smi = 0; smi < 2; ++smi) {
                int rb = (wm << 5) + (smi << 4) + g8;
                a[smi][0] = tf32c(Ab[rb * AS_ST + k0]);
                a[smi][1] = tf32c(Ab[(rb + 8) * AS_ST + k0]);
                a[smi][2] = tf32c(Ab[rb * AS_ST + k0 + 4]);
                a[smi][3] = tf32c(Ab[(rb + 8) * AS_ST + k0 + 4]);
            }
#pragma unroll
            for (int j8 = 0; j8 < 6; ++j8) {
                int n = wn * 48 + (j8 << 3) + g8;
                unsigned b0 = tf32c(Bb[n * AS_ST + k0]);
                unsigned b1 = tf32c(Bb[n * AS_ST + k0 + 4]);
                MMA_TF32(c[0][j8], a[0], b0, b1);
                MMA_TF32(c[1][j8], a[1], b0, b1);
            }
        }
        __syncthreads();
    }

    // ---- stage gates to smem (reuse buffers), Cs[64][200] -----------------
    float* Cs = sm;
    {
        int row0 = (wm << 5) + g8;
        int colb = wn * 48 + (tg << 1);
#pragma unroll
        for (int smi = 0; smi < 2; ++smi)
#pragma unroll
            for (int j8 = 0; j8 < 6; ++j8) {
                int r = row0 + (smi << 4);
                int col = colb + (j8 << 3);
                *(float2*)&Cs[r * CS_ST + col] = make_float2(c[smi][j8][0], c[smi][j8][1]);
                *(float2*)&Cs[(r + 8) * CS_ST + col] = make_float2(c[smi][j8][2], c[smi][j8][3]);
            }
    }
    __syncthreads();

    // ---- fused recurrence epilogue ---------------------------------------
    const int v = tid & 31;
    const int m0 = tid >> 5;                 // 0..7
    float bias[6];
#pragma unroll
    for (int g = 0; g < 6; ++g) bias[g] = Bp[(g << 8) + u0 + v];

#pragma unroll
    for (int i = 0; i < 8; ++i) {
        int m = m0 + (i << 3);
        int n = n0 + m;
        int r = n >> 5;
        float bm = (r <= s && s < RR_) ? 1.0f : 0.0f;
        float G[6];
#pragma unroll
        for (int g = 0; g < 6; ++g) G[g] = Cs[m * CS_ST + (g << 5) + v] + bm * bias[g];
        float u_row = sigf(G[0]), o_row = sigf(G[1]);
        float u_col = sigf(G[2]), o_col = sigf(G[3]);
        float i_row = tanhf_(G[4]), i_col = tanhf_(G[5]);
        float hro = g_h_row[cur][(n << 8) + u0 + v];
        float hco = g_h_col[cur][(n << 8) + u0 + v];
        float hr = tanhf_((1.0f - u_row) * hro + u_row * i_row) * o_row;
        float hc = tanhf_((1.0f - u_col) * hco + u_col * i_col) * o_col;

        size_t ob = ((size_t)n * LL + s) * 512 + u0 + v;
        out[ob]       = hr;
        out[ob + 256] = hc;
        g_h_row[nxt][(n << 8) + u0 + v] = hr;
        int n2 = n + NB; if (n2 >= MM) n2 -= MM;       // roll(h_col, +B)
        g_h_col[nxt][(n2 << 8) + u0 + v] = hc;
    }
}

// ---------------------------------------------------------------------------
__global__ void witran_gather_kernel(float* __restrict__ out) {
    int idx = blockIdx.x * blockDim.x + threadIdx.x;
    if (idx < 393216) {
        int k = idx & 255;
        int t = (idx >> 8) % LORIG;
        int b = idx / (LORIG * 256);
        out[OFF1 + idx] = out[((size_t)(736 + b) * LL + 23 + t) * 512 + 256 + k];
    } else if (idx < 589824) {
        int j = idx - 393216;
        int k = j & 255;
        int i = (j >> 8) % RR_;
        int b = j / (RR_ * 256);
        out[OFF2 + j] = out[((size_t)(i * NB + b) * LL + 47 + i) * 512 + k];
    }
}

// ---------------------------------------------------------------------------
extern "C" void kernel_launch(void* const* d_in, const int* in_sizes, int n_in,
                              void* d_out, int out_size) {
    const float* input = (const float*)d_in[0];
    const float* W     = (const float*)d_in[1];
    const float* Bp    = (const float*)d_in[2];
    float* out = (float*)d_out;

    cudaFuncSetAttribute(witran_step_mma,
                         cudaFuncAttributeMaxDynamicSharedMemorySize, SMEM_BYTES);

    witran_init_kernel<<<768, 256>>>();
    for (int s = 0; s < LL; ++s) {
        witran_step_mma<<<dim3(8, 12), 256, SMEM_BYTES>>>(s, input, W, Bp, out);
    }
    witran_gather_kernel<<<2304, 256>>>(out);
}

// round 11
// speedup vs baseline: 5.5409x; 1.8660x over previous
#include <cuda_runtime.h>
#include <cuda_bf16.h>
#include <math.h>

// ---------------------------------------------------------------------------
// WITRAN 2D-PSGMU encoder — mma.sync tf32, pre-converted fragment-permuted.
//   B=32, R=24, Lorig=48, L=71, H=256, C=32, K=544, M=768
// ---------------------------------------------------------------------------

#define NB     32
#define RR_    24
#define LORIG  48
#define LL     71
#define MM     768
#define OFF1   27918336
#define OFF2   28311552

// linear fp32 carries (for the elementwise recurrence path)
__device__ __align__(1024) float g_h_row[2][MM * 256];
__device__ __align__(1024) float g_h_col[2][MM * 256];
// tf32 fragment-permuted carries (GEMM A operand), [12 blocks][8 chunks][2048]
__device__ __align__(1024) float g_hrp[2][12 * 16384];
__device__ __align__(1024) float g_hcp[2][12 * 16384];
// tf32 fragment-permuted weights: [8 u-tiles][17 chunks][6144]
__device__ __align__(1024) float g_wp[8 * 17 * 6144];
// tf32 fragment-permuted input: [(r*48+l)][1024]
__device__ __align__(1024) float g_xp[24 * 48 * 1024];

// smem: 3 ring buffers x (A 2048 + B 6144) floats
#define BUF_F   8192
#define SMEM_BYTES (3 * BUF_F * 4)
#define CS_ST   200

__device__ __forceinline__ float sigf(float x) {
    return __fdividef(1.0f, 1.0f + __expf(-x));
}
__device__ __forceinline__ float tanhf_(float x) {
    return 1.0f - __fdividef(2.0f, __expf(2.0f * x) + 1.0f);
}
__device__ __forceinline__ unsigned tf32c(float v) {
    unsigned r;
    asm("cvt.rna.tf32.f32 %0, %1;" : "=r"(r) : "f"(v));
    return r;
}

#define MMA_TF32(c, a, b0, b1) \
    asm volatile("mma.sync.aligned.m16n8k8.row.col.f32.tf32.tf32.f32 " \
        "{%0,%1,%2,%3},{%4,%5,%6,%7},{%8,%9},{%0,%1,%2,%3};" \
        : "+f"((c)[0]), "+f"((c)[1]), "+f"((c)[2]), "+f"((c)[3]) \
        : "r"((a).x), "r"((a).y), "r"((a).z), "r"((a).w), \
          "r"(b0), "r"(b1))

// fragment-permuted index inside one 64-row x 32-k chunk (2048 floats)
__device__ __forceinline__ int fragidx(int row64, int kk) {
    int group = row64 >> 4, p = row64 & 15;
    int q = kk >> 3, t = kk & 7, tg = t & 3, i2 = t >> 2;
    return group * 512 + q * 128 + (p & 7) * 16 + tg * 4 + (((p >> 3) & 1) | (i2 << 1));
}

// ---------------------------------------------------------------------------
__global__ void witran_init_kernel(const float* __restrict__ W,
                                   const float* __restrict__ input) {
    int idx0 = blockIdx.x * blockDim.x + threadIdx.x;
    int stride = gridDim.x * blockDim.x;
    for (int i = idx0; i < MM * 256; i += stride) {
        g_h_row[0][i] = 0.0f; g_h_col[0][i] = 0.0f;
        g_hrp[0][i] = 0.0f;   g_hcp[0][i] = 0.0f;   // same element count
    }
    // W permute+convert: W[j][k], j = g*256 + v
    for (int idx = idx0; idx < 1536 * 544; idx += stride) {
        int j = idx / 544, k = idx - j * 544;
        int g = j >> 8, v = j & 255;
        int ut = v >> 5, nrow = (g << 5) + (v & 31);
        int c = k >> 5, kk = k & 31;
        int q = kk >> 3, t = kk & 7, tg = t & 3, i2 = t >> 2;
        g_wp[ut * 104448 + c * 6144 + q * 1536 + nrow * 8 + tg * 2 + i2] =
            __uint_as_float(tf32c(W[idx]));
    }
    // input permute+convert: input[b][l][r][c]
    for (int idx = idx0; idx < 32 * 48 * 24 * 32; idx += stride) {
        int c  = idx & 31;
        int t1 = idx >> 5;
        int r  = t1 % 24;
        int t2 = t1 / 24;
        int l  = t2 % 48;
        int b  = t2 / 48;
        int q = c >> 3, t = c & 7, tg = t & 3, i2 = t >> 2;
        int dst = (r * 48 + l) * 1024 + (b >> 4) * 512 + q * 128 +
                  (b & 7) * 16 + tg * 4 + (((b >> 3) & 1) | (i2 << 1));
        g_xp[dst] = __uint_as_float(tf32c(input[idx]));
    }
}

// ---------------------------------------------------------------------------
// grid (8, 12): bx = 32-unit tile, by = 64-row M tile. 256 threads,
// 8 warps in 2(M) x 4(N), warp tile 32 x 48.
__global__ void __launch_bounds__(256, 1)
witran_step_mma(int s, const float* __restrict__ Bp, float* __restrict__ out) {
    extern __shared__ float sm[];
    const unsigned sbase = (unsigned)__cvta_generic_to_shared(sm);

    const int tid  = threadIdx.x;
    const int wid  = tid >> 5, lane = tid & 31;
    const int g8   = lane >> 2, tg = lane & 3;
    const int wm   = wid & 1,  wn = wid >> 1;
    const int bx   = blockIdx.x, by = blockIdx.y;
    const int u0   = bx << 5;
    const int n0   = by << 6;
    const int cur  = s & 1, nxt = cur ^ 1;

    const float* wsrc = g_wp + bx * 104448;

    auto prefetch = [&](int c, int buf) {
        const unsigned dbase = sbase + buf * (BUF_F * 4);
        const float* asrc = (c < 8) ? (g_hrp[cur] + by * 16384 + c * 2048)
                                    : (g_hcp[cur] + by * 16384 + (c - 8) * 2048);
        const float* bsrc = wsrc + c * 6144;
#pragma unroll
        for (int i = 0; i < 8; ++i) {
            int u = tid + (i << 8);                  // 0..2047 (16B units)
            if (i < 2) {                             // A: units 0..511
                unsigned dst = dbase + u * 16;
                if (c < 16) {
                    asm volatile("cp.async.cg.shared.global [%0], [%1], 16;"
                                 :: "r"(dst), "l"(asrc + u * 4));
                } else {                             // x chunk
                    int group = u >> 7;
                    int r = (by << 1) + (group >> 1);
                    int l = s - r;
                    const float* src; unsigned sz = 16;
                    if (l >= 0 && l < LORIG)
                        src = g_xp + (r * 48 + l) * 1024 +
                              ((group & 1) * 128 + (u & 127)) * 4;
                    else { src = g_xp; sz = 0; }
                    asm volatile("cp.async.cg.shared.global [%0], [%1], 16, %2;"
                                 :: "r"(dst), "l"(src), "r"(sz));
                }
            } else {                                 // B: units 512..2047
                unsigned dst = dbase + 2048 * 4 + (u - 512) * 16;
                asm volatile("cp.async.cg.shared.global [%0], [%1], 16;"
                             :: "r"(dst), "l"(bsrc + (u - 512) * 4));
            }
        }
        asm volatile("cp.async.commit_group;");
    };

    float c[2][6][4];
#pragma unroll
    for (int i = 0; i < 2; ++i)
#pragma unroll
        for (int j = 0; j < 6; ++j)
#pragma unroll
            for (int q = 0; q < 4; ++q) c[i][j][q] = 0.0f;

    prefetch(0, 0);
    prefetch(1, 1);
    int buf = 0, pbuf = 2;
    for (int t = 0; t < 17; ++t) {
        if (t < 16) asm volatile("cp.async.wait_group 1;");
        else        asm volatile("cp.async.wait_group 0;");
        __syncthreads();
        if (t < 15) {
            prefetch(t + 2, pbuf);
            if (++pbuf == 3) pbuf = 0;
        }
        const float* Ab = sm + buf * BUF_F;
        const float* Bb = Ab + 2048;
        if (++buf == 3) buf = 0;
#pragma unroll
        for (int q = 0; q < 4; ++q) {
            uint4 fa0 = *(const uint4*)(Ab + (wm * 2) * 512 + q * 128 + g8 * 16 + tg * 4);
            uint4 fa1 = *(const uint4*)(Ab + (wm * 2 + 1) * 512 + q * 128 + g8 * 16 + tg * 4);
#pragma unroll
            for (int j8 = 0; j8 < 6; ++j8) {
                uint2 fb = *(const uint2*)(Bb + q * 1536 +
                                           (wn * 48 + j8 * 8 + g8) * 8 + tg * 2);
                MMA_TF32(c[0][j8], fa0, fb.x, fb.y);
                MMA_TF32(c[1][j8], fa1, fb.x, fb.y);
            }
        }
    }
    __syncthreads();

    // ---- stage gates to smem, Cs[64][200] ---------------------------------
    float* Cs = sm;
    {
        int row0 = (wm << 5) + g8;
        int colb = wn * 48 + (tg << 1);
#pragma unroll
        for (int smi = 0; smi < 2; ++smi)
#pragma unroll
            for (int j8 = 0; j8 < 6; ++j8) {
                int r = row0 + (smi << 4);
                int col = colb + (j8 << 3);
                *(float2*)&Cs[r * CS_ST + col] = make_float2(c[smi][j8][0], c[smi][j8][1]);
                *(float2*)&Cs[(r + 8) * CS_ST + col] = make_float2(c[smi][j8][2], c[smi][j8][3]);
            }
    }
    __syncthreads();

    // ---- fused recurrence epilogue ---------------------------------------
    const int v = tid & 31;
    const int m0 = tid >> 5;
    float bias[6];
#pragma unroll
    for (int g = 0; g < 6; ++g) bias[g] = Bp[(g << 8) + u0 + v];

#pragma unroll
    for (int i = 0; i < 8; ++i) {
        int m = m0 + (i << 3);
        int n = n0 + m;
        int r = n >> 5;
        float bm = (r <= s && s < RR_) ? 1.0f : 0.0f;
        float G[6];
#pragma unroll
        for (int g = 0; g < 6; ++g) G[g] = Cs[m * CS_ST + (g << 5) + v] + bm * bias[g];
        float u_row = sigf(G[0]), o_row = sigf(G[1]);
        float u_col = sigf(G[2]), o_col = sigf(G[3]);
        float i_row = tanhf_(G[4]), i_col = tanhf_(G[5]);
        float hro = g_h_row[cur][(n << 8) + u0 + v];
        float hco = g_h_col[cur][(n << 8) + u0 + v];
        float hr = tanhf_((1.0f - u_row) * hro + u_row * i_row) * o_row;
        float hc = tanhf_((1.0f - u_col) * hco + u_col * i_col) * o_col;

        size_t ob = ((size_t)n * LL + s) * 512 + u0 + v;
        out[ob]       = hr;
        out[ob + 256] = hc;
        g_h_row[nxt][(n << 8) + u0 + v] = hr;
        int n2 = n + NB; if (n2 >= MM) n2 -= MM;       // roll(h_col, +B)
        g_h_col[nxt][(n2 << 8) + u0 + v] = hc;

        // tf32 fragment-permuted carries for next step's GEMM A operand
        int fi = fragidx(m, v);
        g_hrp[nxt][by * 16384 + bx * 2048 + fi] = __uint_as_float(tf32c(hr));
        int blk2 = n2 >> 6, m2 = n2 & 63;
        g_hcp[nxt][blk2 * 16384 + bx * 2048 + fragidx(m2, v)] = __uint_as_float(tf32c(hc));
    }
}

// ---------------------------------------------------------------------------
__global__ void witran_gather_kernel(float* __restrict__ out) {
    int idx = blockIdx.x * blockDim.x + threadIdx.x;
    if (idx < 393216) {
        int k = idx & 255;
        int t = (idx >> 8) % LORIG;
        int b = idx / (LORIG * 256);
        out[OFF1 + idx] = out[((size_t)(736 + b) * LL + 23 + t) * 512 + 256 + k];
    } else if (idx < 589824) {
        int j = idx - 393216;
        int k = j & 255;
        int i = (j >> 8) % RR_;
        int b = j / (RR_ * 256);
        out[OFF2 + j] = out[((size_t)(i * NB + b) * LL + 47 + i) * 512 + k];
    }
}

// ---------------------------------------------------------------------------
extern "C" void kernel_launch(void* const* d_in, const int* in_sizes, int n_in,
                              void* d_out, int out_size) {
    const float* input = (const float*)d_in[0];
    const float* W     = (const float*)d_in[1];
    const float* Bp    = (const float*)d_in[2];
    float* out = (float*)d_out;

    cudaFuncSetAttribute(witran_step_mma,
                         cudaFuncAttributeMaxDynamicSharedMemorySize, SMEM_BYTES);

    witran_init_kernel<<<1024, 256>>>(W, input);
    for (int s = 0; s < LL; ++s) {
        witran_step_mma<<<dim3(8, 12), 256, SMEM_BYTES>>>(s, Bp, out);
    }
    witran_gather_kernel<<<2304, 256>>>(out);
}